// round 11
// baseline (speedup 1.0000x reference)
#include <cuda_runtime.h>
#include <cuda_bf16.h>

// SiLU(x) = x * sigmoid(x), elementwise, n = 134217728 fp32.
// HBM-bound stream at the ~86% mixed R/W ceiling (~6.8 TB/s measured).
// R6-winner geometry (512 threads, 4 front-batched 128-bit loads, no guards)
// with loads routed through the non-coherent path, evict-first
// (ld.global.nc.cs.v4.f32) and evict-first stores (st.global.cs.v4.f32).

__device__ __forceinline__ float silu1(float x) {
    float s = 1.0f / (1.0f + __expf(-x));
    return x * s;
}

__device__ __forceinline__ float4 silu4(float4 v) {
    float4 r;
    r.x = silu1(v.x);
    r.y = silu1(v.y);
    r.z = silu1(v.z);
    r.w = silu1(v.w);
    return r;
}

__device__ __forceinline__ float4 ldg_nc_cs(const float4* p) {
    float4 v;
    asm volatile("ld.global.nc.cs.v4.f32 {%0,%1,%2,%3}, [%4];"
                 : "=f"(v.x), "=f"(v.y), "=f"(v.z), "=f"(v.w)
                 : "l"(p));
    return v;
}

__device__ __forceinline__ void stg_cs(float4* p, float4 v) {
    asm volatile("st.global.cs.v4.f32 [%0], {%1,%2,%3,%4};"
                 :: "l"(p), "f"(v.x), "f"(v.y), "f"(v.z), "f"(v.w)
                 : "memory");
}

// Full-tile kernel: every block owns exactly 2048 float4s, no guards.
__global__ void __launch_bounds__(512) silu_b512_nc_kernel(
    const float4* __restrict__ in, float4* __restrict__ out)
{
    unsigned base = blockIdx.x * 2048u + threadIdx.x;
    float4 v0 = ldg_nc_cs(in + base);
    float4 v1 = ldg_nc_cs(in + base + 512);
    float4 v2 = ldg_nc_cs(in + base + 1024);
    float4 v3 = ldg_nc_cs(in + base + 1536);
    stg_cs(out + base,        silu4(v0));
    stg_cs(out + base + 512,  silu4(v1));
    stg_cs(out + base + 1024, silu4(v2));
    stg_cs(out + base + 1536, silu4(v3));
}

// Generic guarded kernel (fallback for shapes not divisible by tile).
__global__ void __launch_bounds__(256) silu_guarded_kernel(
    const float4* __restrict__ in, float4* __restrict__ out, int n4)
{
    int base = blockIdx.x * 1024 + threadIdx.x;
    #pragma unroll
    for (int k = 0; k < 4; k++) {
        int i = base + k * 256;
        if (i < n4) __stcs(out + i, silu4(__ldcs(in + i)));
    }
}

// Tail for n not divisible by 4 (not hit for this shape).
__global__ void silu_tail_kernel(const float* __restrict__ in,
                                 float* __restrict__ out, int start, int n)
{
    int i = start + blockIdx.x * blockDim.x + threadIdx.x;
    if (i < n) out[i] = silu1(in[i]);
}

extern "C" void kernel_launch(void* const* d_in, const int* in_sizes, int n_in,
                              void* d_out, int out_size)
{
    const float* x = (const float*)d_in[0];
    float* y = (float*)d_out;
    int n = in_sizes[0];

    int n4 = n / 4;
    if (n4 > 0) {
        if ((n4 & 2047) == 0) {
            silu_b512_nc_kernel<<<n4 / 2048, 512>>>(
                (const float4*)x, (float4*)y);
        } else {
            silu_guarded_kernel<<<(n4 + 1023) / 1024, 256>>>(
                (const float4*)x, (float4*)y, n4);
        }
    }
    int rem = n - n4 * 4;
    if (rem > 0) {
        silu_tail_kernel<<<1, 256>>>(x, y, n4 * 4, n);
    }
}

// round 12
// speedup vs baseline: 1.0084x; 1.0084x over previous
#include <cuda_runtime.h>
#include <cuda_bf16.h>

// SiLU(x) = x * sigmoid(x), elementwise, n = 134217728 fp32.
// FINAL: HBM-bound stream at the measured ~86%-of-spec mixed R/W ceiling
// (~6.8 TB/s). 512-thread blocks, 4 front-batched LDG.128 per thread (MLP=4),
// tile = 2048 float4s, grid = 16384, evict-first hints, no guards on fast path.
// This operating point won a 10-configuration sweep (MLP 1-8, block 256-1024,
// persistent, TMA bulk, 256-bit v8 ops, tanh MUFU, NC path).

__device__ __forceinline__ float silu1(float x) {
    float s = 1.0f / (1.0f + __expf(-x));
    return x * s;
}

__device__ __forceinline__ float4 silu4(float4 v) {
    float4 r;
    r.x = silu1(v.x);
    r.y = silu1(v.y);
    r.z = silu1(v.z);
    r.w = silu1(v.w);
    return r;
}

// Full-tile kernel: every block owns exactly 2048 float4s, no guards.
__global__ void __launch_bounds__(512) silu_b512_full_kernel(
    const float4* __restrict__ in, float4* __restrict__ out)
{
    unsigned base = blockIdx.x * 2048u + threadIdx.x;
    float4 v0 = __ldcs(in + base);
    float4 v1 = __ldcs(in + base + 512);
    float4 v2 = __ldcs(in + base + 1024);
    float4 v3 = __ldcs(in + base + 1536);
    __stcs(out + base,        silu4(v0));
    __stcs(out + base + 512,  silu4(v1));
    __stcs(out + base + 1024, silu4(v2));
    __stcs(out + base + 1536, silu4(v3));
}

// Generic guarded kernel (fallback for shapes not divisible by tile).
__global__ void __launch_bounds__(256) silu_guarded_kernel(
    const float4* __restrict__ in, float4* __restrict__ out, int n4)
{
    int base = blockIdx.x * 1024 + threadIdx.x;
    #pragma unroll
    for (int k = 0; k < 4; k++) {
        int i = base + k * 256;
        if (i < n4) __stcs(out + i, silu4(__ldcs(in + i)));
    }
}

// Tail for n not divisible by 4 (not hit for this shape).
__global__ void silu_tail_kernel(const float* __restrict__ in,
                                 float* __restrict__ out, int start, int n)
{
    int i = start + blockIdx.x * blockDim.x + threadIdx.x;
    if (i < n) out[i] = silu1(in[i]);
}

extern "C" void kernel_launch(void* const* d_in, const int* in_sizes, int n_in,
                              void* d_out, int out_size)
{
    const float* x = (const float*)d_in[0];
    float* y = (float*)d_out;
    int n = in_sizes[0];

    int n4 = n / 4;
    if (n4 > 0) {
        if ((n4 & 2047) == 0) {
            // exact full tiles — no-guard fast path, 512-thread blocks
            silu_b512_full_kernel<<<n4 / 2048, 512>>>(
                (const float4*)x, (float4*)y);
        } else {
            silu_guarded_kernel<<<(n4 + 1023) / 1024, 256>>>(
                (const float4*)x, (float4*)y, n4);
        }
    }
    int rem = n - n4 * 4;
    if (rem > 0) {
        silu_tail_kernel<<<1, 256>>>(x, y, n4 * 4, n);
    }
}